// round 16
// baseline (speedup 1.0000x reference)
#include <cuda_runtime.h>
#include <cuda_bf16.h>
#include <math.h>
#include <stdint.h>

#define NN    50000
#define EE    800000
#define EP1   (EE + NN)
#define INC   512
#define HID   256
#define OUTC  2
#define EPSV  1e-5f

// ---------------------------------------------------------------------------
// Device scratch (no allocation allowed)
// ---------------------------------------------------------------------------
__device__ int   d_flag;
__device__ float d_deg[NN];
__device__ int   d_rows[EP1];
__device__ int   d_cols[EP1];
__device__ int   d_rowptr[NN + 1];
__device__ int   d_cursor[NN];
__device__ int   d_csr_col[EP1];
__device__ float d_csr_w[EP1];
__device__ float d_stats[2 * HID];
__device__ int   d_bsum[256];
__device__ int   d_boff[256];
__device__ int   d_rowtmp[NN];

// fp32 intermediates
__device__ float bufA[(size_t)NN * HID];
__device__ float bufB[(size_t)NN * HID];

// bf16 hi/lo activation pairs
__device__ __nv_bfloat16 bXh[(size_t)NN * INC];
__device__ __nv_bfloat16 bXl[(size_t)NN * INC];
__device__ __nv_bfloat16 bHh[(size_t)NN * HID];
__device__ __nv_bfloat16 bHl[(size_t)NN * HID];
__device__ __nv_bfloat16 bG0h[(size_t)NN * HID];
__device__ __nv_bfloat16 bG0l[(size_t)NN * HID];
__device__ __nv_bfloat16 bG1h[(size_t)NN * HID];
__device__ __nv_bfloat16 bG1l[(size_t)NN * HID];
__device__ __nv_bfloat16 bG2h[(size_t)NN * HID];
__device__ __nv_bfloat16 bG2l[(size_t)NN * HID];
__device__ __nv_bfloat16 bLh[(size_t)NN * HID];
__device__ __nv_bfloat16 bLl[(size_t)NN * HID];

// transposed bf16 weights, [N=256, K] per segment
#define WT_TOTAL 786432
__device__ __nv_bfloat16 d_wth[WT_TOTAL];
__device__ __nv_bfloat16 d_wtl[WT_TOTAL];

// ---------------------------------------------------------------------------
// mma.sync / ldmatrix helpers (base-target legal, no tcgen05)
// ---------------------------------------------------------------------------
__device__ __forceinline__ uint32_t smem_u32(const void* p) {
    uint32_t a;
    asm("{ .reg .u64 t; cvta.to.shared.u64 t, %1; cvt.u32.u64 %0, t; }" : "=r"(a) : "l"(p));
    return a;
}
__device__ __forceinline__ void ldsm4(uint32_t* r, uint32_t addr) {
    asm volatile("ldmatrix.sync.aligned.m8n8.x4.shared.b16 {%0,%1,%2,%3}, [%4];"
                 : "=r"(r[0]), "=r"(r[1]), "=r"(r[2]), "=r"(r[3]) : "r"(addr));
}
__device__ __forceinline__ void mma16816(float* d, const uint32_t* a,
                                         uint32_t b0, uint32_t b1) {
    asm volatile(
        "mma.sync.aligned.m16n8k16.row.col.f32.bf16.bf16.f32 "
        "{%0,%1,%2,%3}, {%4,%5,%6,%7}, {%8,%9}, {%0,%1,%2,%3};"
        : "+f"(d[0]), "+f"(d[1]), "+f"(d[2]), "+f"(d[3])
        : "r"(a[0]), "r"(a[1]), "r"(a[2]), "r"(a[3]), "r"(b0), "r"(b1));
}

// ---------------------------------------------------------------------------
// Preprocessing
// ---------------------------------------------------------------------------
__global__ void zero_pre_kernel() {
    int i = blockIdx.x * blockDim.x + threadIdx.x;
    if (i < NN) { d_deg[i] = 0.0f; d_cursor[i] = 0; }
}
__global__ void detect_kernel(const unsigned int* __restrict__ ei) {
    if (threadIdx.x == 0 && blockIdx.x == 0) {
        int is64 = 1;
        for (int k = 0; k < 256; k++)
            if (ei[2 * k + 1] != 0u) { is64 = 0; break; }
        d_flag = is64;
    }
}
__global__ void build_edges_kernel(const void* __restrict__ ei) {
    int e = blockIdx.x * blockDim.x + threadIdx.x;
    if (e >= EP1) return;
    int r, c;
    if (e < EE) {
        if (d_flag) {
            const long long* p = (const long long*)ei;
            r = (int)p[e]; c = (int)p[EE + e];
        } else {
            const int* p = (const int*)ei;
            r = p[e]; c = p[EE + e];
        }
    } else {
        r = c = e - EE;
    }
    d_rows[e] = r;
    d_cols[e] = c;
    atomicAdd(&d_deg[r], 1.0f);
}
__global__ void scan1_kernel() {
    __shared__ int sh[256];
    int b = blockIdx.x, t = threadIdx.x;
    int i = b * 256 + t;
    sh[t] = (i < NN) ? (int)d_deg[i] : 0;
    __syncthreads();
    for (int off = 1; off < 256; off <<= 1) {
        int add = (t >= off) ? sh[t - off] : 0;
        __syncthreads();
        sh[t] += add;
        __syncthreads();
    }
    if (i < NN) d_rowtmp[i] = sh[t];
    if (t == 255) d_bsum[b] = sh[255];
}
__global__ void scan2_kernel() {
    __shared__ int sh[256];
    int t = threadIdx.x;
    sh[t] = (t < 196) ? d_bsum[t] : 0;
    __syncthreads();
    for (int off = 1; off < 256; off <<= 1) {
        int add = (t >= off) ? sh[t - off] : 0;
        __syncthreads();
        sh[t] += add;
        __syncthreads();
    }
    d_boff[t] = (t == 0) ? 0 : sh[t - 1];
}
__global__ void scan3_kernel() {
    int i = blockIdx.x * blockDim.x + threadIdx.x;
    if (i >= NN) return;
    if (i == 0) d_rowptr[0] = 0;
    d_rowptr[i + 1] = d_rowtmp[i] + d_boff[i >> 8];
}
__global__ void csr_build_kernel() {
    int e = blockIdx.x * blockDim.x + threadIdx.x;
    if (e >= EP1) return;
    int r = d_rows[e], c = d_cols[e];
    float w = rsqrtf(d_deg[r]) * rsqrtf(d_deg[c]);
    int pos = d_rowptr[r] + atomicAdd(&d_cursor[r], 1);
    d_csr_col[pos] = c;
    d_csr_w[pos]   = w;
}

// ---------------------------------------------------------------------------
// Weight transpose + bf16 split: Wt[n,k] = W[k,n], hi/lo
// ---------------------------------------------------------------------------
__global__ void wt_kernel(const float* __restrict__ w0, const float* __restrict__ cws,
                          const float* __restrict__ g0, const float* __restrict__ gws,
                          const float* __restrict__ fl)
{
    int i = blockIdx.x * blockDim.x + threadIdx.x;
    if (i >= WT_TOTAL) return;
    const float* src; int K, base;
    if      (i < 131072) { base = 0;      src = w0;            K = 512; }
    else if (i < 196608) { base = 131072; src = cws;           K = 256; }
    else if (i < 262144) { base = 196608; src = cws + 65536;   K = 256; }
    else if (i < 327680) { base = 262144; src = g0;            K = 256; }
    else if (i < 458752) { base = 327680; src = gws;           K = 512; }
    else if (i < 589824) { base = 458752; src = gws + 131072;  K = 512; }
    else if (i < 655360) { base = 589824; src = fl;            K = 256; }
    else if (i < 720896) { base = 655360; src = fl + 65536;    K = 256; }
    else                 { base = 720896; src = fl + 131072;   K = 256; }
    int idx = i - base;
    int n = idx / K, k = idx - n * K;
    float v = src[k * 256 + n];
    __nv_bfloat16 h = __float2bfloat16(v);
    d_wth[i] = h;
    d_wtl[i] = __float2bfloat16(v - __bfloat162float(h));
}

__global__ void cvt_x_kernel(const float* __restrict__ x) {
    int i = blockIdx.x * blockDim.x + threadIdx.x;
    if (i >= NN * INC) return;
    float v = x[i];
    __nv_bfloat16 h = __float2bfloat16(v);
    bXh[i] = h;
    bXl[i] = __float2bfloat16(v - __bfloat162float(h));
}

// ---------------------------------------------------------------------------
// bf16-split GEMM via mma.sync.m16n8k16:
//   C[M,256] = (A1h+A1l | A2h+A2l)[M,K1+K2] @ Wt^T
//   3 precision terms accumulated in one fp32 accumulator:
//   Ah*Wh + Ah*Wl + Al*Wh.
// CTA 128x128, 8 warps (4 M x 2 N), warp tile 32x64, BK=32 double-buffered.
// ---------------------------------------------------------------------------
#define GBM 128
#define GBN 128
#define ASTRIDE 40                       // 32 + 8 pad (bf16 elems)
#define ABUF (128 * ASTRIDE * 2)         // 10240 B per operand per stage
#define GBUF (2 * ABUF)                  // 20480 B per stage

__global__ __launch_bounds__(256)
void mma_gemm_kernel(const __nv_bfloat16* __restrict__ A1h, const __nv_bfloat16* __restrict__ A1l, int K1,
                     const __nv_bfloat16* __restrict__ A2h, const __nv_bfloat16* __restrict__ A2l, int K2,
                     const __nv_bfloat16* __restrict__ Wh,  const __nv_bfloat16* __restrict__ Wl,
                     const float* __restrict__ bias, float* __restrict__ C, int M)
{
    __shared__ char smem[2 * GBUF];
    const int tid  = threadIdx.x;
    const int lane = tid & 31;
    const int wid  = tid >> 5;
    const int wm   = wid & 3;            // 4 warps along M
    const int wn   = wid >> 2;           // 2 warps along N
    const int bm   = blockIdx.y * GBM;
    const int bn   = blockIdx.x * GBN;
    const int Ktot = K1 + K2;
    const int cpt  = Ktot >> 5;          // 32-K chunks per precision term
    const int T    = 3 * cpt;

    float acc[2][8][4];
#pragma unroll
    for (int i = 0; i < 2; i++)
#pragma unroll
        for (int j = 0; j < 8; j++)
#pragma unroll
            for (int q = 0; q < 4; q++) acc[i][j][q] = 0.0f;

    const int lrow = tid >> 2;           // 0..63
    const int lseg = tid & 3;            // 4 segments x 8 bf16 = 32 K

    uint4 pa[2], pb[2];
    auto g_load = [&](int t) {
        int term = t / cpt;
        int kk   = (t - term * cpt) << 5;
        const __nv_bfloat16* Ab; int lda, ko;
        if (kk < K1) { Ab = (term == 2) ? A1l : A1h; lda = K1; ko = kk; }
        else         { Ab = (term == 2) ? A2l : A2h; lda = K2; ko = kk - K1; }
        const __nv_bfloat16* Wb = (term == 1) ? Wl : Wh;
#pragma unroll
        for (int it = 0; it < 2; it++) {
            int row = lrow + it * 64;
            int gr  = bm + row; if (gr >= M) gr = M - 1;
            pa[it] = *(const uint4*)(Ab + (size_t)gr * lda + ko + lseg * 8);
            pb[it] = *(const uint4*)(Wb + (size_t)(bn + row) * Ktot + kk + lseg * 8);
        }
    };
    auto s_store = [&](int buf) {
        char* As = smem + buf * GBUF;
        char* Bs = As + ABUF;
#pragma unroll
        for (int it = 0; it < 2; it++) {
            int row = lrow + it * 64;
            *(uint4*)(As + (row * ASTRIDE + lseg * 8) * 2) = pa[it];
            *(uint4*)(Bs + (row * ASTRIDE + lseg * 8) * 2) = pb[it];
        }
    };

    const uint32_t smb = smem_u32(smem);
    // ldmatrix lane-address bases (A: m16k16 x4; B: n16k16 x4 from [n][k] layout)
    const uint32_t aoff = ((wm * 32 + (lane & 15)) * ASTRIDE + (lane >> 4) * 8) * 2;
    const uint32_t boff = ABUF +
        ((wn * 64 + (lane & 7) + ((lane >> 4) << 3)) * ASTRIDE + ((lane >> 3) & 1) * 8) * 2;

    g_load(0);
    s_store(0);
    __syncthreads();

    for (int t = 0; t < T; t++) {
        const int buf = t & 1;
        if (t + 1 < T) g_load(t + 1);
        const uint32_t base = smb + buf * GBUF;
#pragma unroll
        for (int ks = 0; ks < 2; ks++) {
            uint32_t af[2][4];
#pragma unroll
            for (int i = 0; i < 2; i++)
                ldsm4(af[i], base + aoff + i * (16 * ASTRIDE * 2) + ks * 32);
            uint32_t bf[4][4];
#pragma unroll
            for (int j = 0; j < 4; j++)
                ldsm4(bf[j], base + boff + j * (16 * ASTRIDE * 2) + ks * 32);
#pragma unroll
            for (int i = 0; i < 2; i++)
#pragma unroll
                for (int j = 0; j < 4; j++) {
                    mma16816(acc[i][2 * j + 0], af[i], bf[j][0], bf[j][1]);
                    mma16816(acc[i][2 * j + 1], af[i], bf[j][2], bf[j][3]);
                }
        }
        if (t + 1 < T) s_store(buf ^ 1);
        __syncthreads();
    }

    // epilogue: D fragment (row = l>>2 (+8), col = (l&3)*2)
#pragma unroll
    for (int i = 0; i < 2; i++) {
        int r0 = bm + wm * 32 + i * 16 + (lane >> 2);
#pragma unroll
        for (int j = 0; j < 8; j++) {
            int col = bn + wn * 64 + j * 8 + (lane & 3) * 2;
            float b0 = bias ? bias[col]     : 0.0f;
            float b1 = bias ? bias[col + 1] : 0.0f;
            if (r0 < M) {
                float2 v = { acc[i][j][0] + b0, acc[i][j][1] + b1 };
                *(float2*)(C + (size_t)r0 * 256 + col) = v;
            }
            if (r0 + 8 < M) {
                float2 v = { acc[i][j][2] + b0, acc[i][j][3] + b1 };
                *(float2*)(C + (size_t)(r0 + 8) * 256 + col) = v;
            }
        }
    }
}

// ---------------------------------------------------------------------------
// SpMM (CSR, warp per row): dst[r,:] = sum_e w_e * src[col_e,:] + bias[:]
// ---------------------------------------------------------------------------
__global__ void spmm_kernel(const float* __restrict__ src,
                            const float* __restrict__ bias,
                            float* __restrict__ dst)
{
    int gw   = (blockIdx.x * blockDim.x + threadIdx.x) >> 5;
    int lane = threadIdx.x & 31;
    if (gw >= NN) return;
    int beg = d_rowptr[gw], end = d_rowptr[gw + 1];
    float acc[8] = {0, 0, 0, 0, 0, 0, 0, 0};
    for (int e = beg; e < end; e++) {
        int   cidx = d_csr_col[e];
        float w    = d_csr_w[e];
        const float* p = src + (size_t)cidx * HID;
#pragma unroll
        for (int k = 0; k < 8; k++) acc[k] += w * p[lane + 32 * k];
    }
    float* o = dst + (size_t)gw * HID;
#pragma unroll
    for (int k = 0; k < 8; k++) o[lane + 32 * k] = acc[k] + bias[lane + 32 * k];
}

// ---------------------------------------------------------------------------
// BatchNorm
// ---------------------------------------------------------------------------
__global__ void zero_stats_kernel() {
    int i = blockIdx.x * blockDim.x + threadIdx.x;
    if (i < 2 * HID) d_stats[i] = 0.0f;
}
__global__ void stats_kernel(const float* __restrict__ src) {
    int c  = threadIdx.x;
    int r0 = blockIdx.x * 64;
    int r1 = r0 + 64; if (r1 > NN) r1 = NN;
    float s = 0.0f, s2 = 0.0f;
    for (int r = r0; r < r1; r++) {
        float v = src[(size_t)r * HID + c];
        s += v; s2 += v * v;
    }
    atomicAdd(&d_stats[c], s);
    atomicAdd(&d_stats[HID + c], s2);
}
__global__ void bnrelu_pair_kernel(const float* __restrict__ src,
                                   __nv_bfloat16* __restrict__ dh,
                                   __nv_bfloat16* __restrict__ dl,
                                   const float* __restrict__ g,
                                   const float* __restrict__ b)
{
    int i = blockIdx.x * blockDim.x + threadIdx.x;
    if (i >= NN * HID) return;
    int c = i & (HID - 1);
    const float invn = 1.0f / (float)NN;
    float m = d_stats[c] * invn;
    float v = d_stats[HID + c] * invn - m * m;
    float s = g[c] * rsqrtf(v + EPSV);
    float y = fmaxf((src[i] - m) * s + b[c], 0.0f);
    __nv_bfloat16 h = __float2bfloat16(y);
    dh[i] = h;
    dl[i] = __float2bfloat16(y - __bfloat162float(h));
}

// ---------------------------------------------------------------------------
// Head: out[hidx, r, :] = log_softmax((hi+lo)[r,:] @ W[256,2] + b)
// ---------------------------------------------------------------------------
__global__ void head_kernel(const __nv_bfloat16* __restrict__ hh,
                            const __nv_bfloat16* __restrict__ hl,
                            const float* __restrict__ W,
                            const float* __restrict__ b,
                            float* __restrict__ out, int hidx)
{
    int gw   = (blockIdx.x * blockDim.x + threadIdx.x) >> 5;
    int lane = threadIdx.x & 31;
    if (gw >= NN) return;
    const __nv_bfloat16* ph = hh + (size_t)gw * HID;
    const __nv_bfloat16* pl = hl + (size_t)gw * HID;
    float a0 = 0.0f, a1 = 0.0f;
#pragma unroll
    for (int k = lane; k < HID; k += 32) {
        float v = __bfloat162float(ph[k]) + __bfloat162float(pl[k]);
        a0 += v * W[2 * k];
        a1 += v * W[2 * k + 1];
    }
#pragma unroll
    for (int off = 16; off; off >>= 1) {
        a0 += __shfl_down_sync(0xffffffffu, a0, off);
        a1 += __shfl_down_sync(0xffffffffu, a1, off);
    }
    if (lane == 0) {
        float z0 = a0 + b[0], z1 = a1 + b[1];
        float m  = fmaxf(z0, z1);
        float l  = m + logf(expf(z0 - m) + expf(z1 - m));
        float* o = out + ((size_t)hidx * NN + gw) * 2;
        o[0] = z0 - l;
        o[1] = z1 - l;
    }
}

// ---------------------------------------------------------------------------
// Host launcher
// ---------------------------------------------------------------------------
extern "C" void kernel_launch(void* const* d_in, const int* in_sizes, int n_in,
                              void* d_out, int out_size)
{
    const float* x       = (const float*)d_in[0];
    const void*  ei      = d_in[1];
    const float* conv_w0 = (const float*)d_in[2];
    const float* conv_ws = (const float*)d_in[3];
    const float* conv_b  = (const float*)d_in[4];
    const float* bn_g    = (const float*)d_in[5];
    const float* bn_b    = (const float*)d_in[6];
    const float* fcg_w0  = (const float*)d_in[7];
    const float* fcg_ws  = (const float*)d_in[8];
    const float* fcg_b   = (const float*)d_in[9];
    const float* bng_g   = (const float*)d_in[10];
    const float* bng_b   = (const float*)d_in[11];
    const float* fcl_w   = (const float*)d_in[12];
    const float* fcl_b   = (const float*)d_in[13];
    const float* bnl_g   = (const float*)d_in[14];
    const float* bnl_b   = (const float*)d_in[15];
    const float* outg_w  = (const float*)d_in[16];
    const float* outg_b  = (const float*)d_in[17];
    const float* outl_w  = (const float*)d_in[18];
    const float* outl_b  = (const float*)d_in[19];
    float* out = (float*)d_out;

    float *pA, *pB;
    __nv_bfloat16 *pXh, *pXl, *pHh, *pHl, *pG0h, *pG0l, *pG1h, *pG1l, *pG2h, *pG2l, *pLh, *pLl;
    __nv_bfloat16 *pWh, *pWl;
    cudaGetSymbolAddress((void**)&pA,  bufA);
    cudaGetSymbolAddress((void**)&pB,  bufB);
    cudaGetSymbolAddress((void**)&pXh, bXh);  cudaGetSymbolAddress((void**)&pXl, bXl);
    cudaGetSymbolAddress((void**)&pHh, bHh);  cudaGetSymbolAddress((void**)&pHl, bHl);
    cudaGetSymbolAddress((void**)&pG0h, bG0h); cudaGetSymbolAddress((void**)&pG0l, bG0l);
    cudaGetSymbolAddress((void**)&pG1h, bG1h); cudaGetSymbolAddress((void**)&pG1l, bG1l);
    cudaGetSymbolAddress((void**)&pG2h, bG2h); cudaGetSymbolAddress((void**)&pG2l, bG2l);
    cudaGetSymbolAddress((void**)&pLh, bLh);  cudaGetSymbolAddress((void**)&pLl, bLl);
    cudaGetSymbolAddress((void**)&pWh, d_wth); cudaGetSymbolAddress((void**)&pWl, d_wtl);

    // ---- preprocessing ----
    zero_pre_kernel<<<(NN + 255) / 256, 256>>>();
    detect_kernel<<<1, 32>>>((const unsigned int*)ei);
    build_edges_kernel<<<(EP1 + 255) / 256, 256>>>(ei);
    scan1_kernel<<<196, 256>>>();
    scan2_kernel<<<1, 256>>>();
    scan3_kernel<<<(NN + 255) / 256, 256>>>();
    csr_build_kernel<<<(EP1 + 255) / 256, 256>>>();

    wt_kernel<<<(WT_TOTAL + 255) / 256, 256>>>(conv_w0, conv_ws, fcg_w0, fcg_ws, fcl_w);
    cvt_x_kernel<<<(NN * INC + 255) / 256, 256>>>(x);

    dim3 gg(2, (NN + GBM - 1) / GBM);    // 2 x 391
    const int spmm_grid = (NN + 7) / 8;
    const int head_grid = (NN + 7) / 8;

    auto bn_pair = [&](const float* src, __nv_bfloat16* dh, __nv_bfloat16* dl,
                       const float* g, const float* b) {
        zero_stats_kernel<<<2, 256>>>();
        stats_kernel<<<(NN + 63) / 64, 256>>>(src);
        bnrelu_pair_kernel<<<(NN * HID + 255) / 256, 256>>>(src, dh, dl, g, b);
    };

    const int W0 = 0, C1 = 131072, C2 = 196608, G0 = 262144,
              GW0 = 327680, GW1 = 458752, L0 = 589824, L1 = 655360, L2 = 720896;

    // ---- GCN layers ----
    mma_gemm_kernel<<<gg, 256>>>(pXh, pXl, INC, nullptr, nullptr, 0,
                                 pWh + W0, pWl + W0, nullptr, pA, NN);
    spmm_kernel<<<spmm_grid, 256>>>(pA, conv_b + 0 * HID, pB);
    bn_pair(pB, pHh, pHl, bn_g + 0 * HID, bn_b + 0 * HID);

    const int cofs[2] = { C1, C2 };
    for (int i = 1; i < 3; i++) {
        mma_gemm_kernel<<<gg, 256>>>(pHh, pHl, HID, nullptr, nullptr, 0,
                                     pWh + cofs[i - 1], pWl + cofs[i - 1],
                                     nullptr, pA, NN);
        spmm_kernel<<<spmm_grid, 256>>>(pA, conv_b + (size_t)i * HID, pB);
        bn_pair(pB, pHh, pHl, bn_g + (size_t)i * HID, bn_b + (size_t)i * HID);
    }

    // ---- hierarchical global path ----
    mma_gemm_kernel<<<gg, 256>>>(pHh, pHl, HID, nullptr, nullptr, 0,
                                 pWh + G0, pWl + G0, fcg_b + 0 * HID, pA, NN);
    bn_pair(pA, pG0h, pG0l, bng_g + 0 * HID, bng_b + 0 * HID);

    __nv_bfloat16* gh[3] = { pG0h, pG1h, pG2h };
    __nv_bfloat16* gl[3] = { pG0l, pG1l, pG2l };
    const int gwofs[2] = { GW0, GW1 };
    for (int i = 0; i < 2; i++) {
        // concat([hg[i], h]) @ W — single K=512 GEMM with two A sources
        mma_gemm_kernel<<<gg, 256>>>(gh[i], gl[i], HID, pHh, pHl, HID,
                                     pWh + gwofs[i], pWl + gwofs[i],
                                     fcg_b + (size_t)(i + 1) * HID, pA, NN);
        bn_pair(pA, gh[i + 1], gl[i + 1],
                bng_g + (size_t)(i + 1) * HID, bng_b + (size_t)(i + 1) * HID);
    }

    // ---- global head ----
    head_kernel<<<head_grid, 256>>>(pG2h, pG2l, outg_w, outg_b, out, 0);

    // ---- local heads ----
    const int lofs[3] = { L0, L1, L2 };
    for (int i = 0; i < 3; i++) {
        mma_gemm_kernel<<<gg, 256>>>(gh[i], gl[i], HID, nullptr, nullptr, 0,
                                     pWh + lofs[i], pWl + lofs[i],
                                     fcl_b + (size_t)i * HID, pA, NN);
        bn_pair(pA, pLh, pLl, bnl_g + (size_t)i * HID, bnl_b + (size_t)i * HID);
        head_kernel<<<head_grid, 256>>>(pLh, pLl, outl_w + (size_t)i * HID * OUTC,
                                        outl_b + (size_t)i * OUTC, out, 1 + i);
    }
}

// round 17
// speedup vs baseline: 1.1187x; 1.1187x over previous
#include <cuda_runtime.h>
#include <cuda_bf16.h>
#include <math.h>
#include <stdint.h>

#define NN    50000
#define EE    800000
#define EP1   (EE + NN)
#define INC   512
#define HID   256
#define OUTC  2
#define EPSV  1e-5f

// ---------------------------------------------------------------------------
// Device scratch (no allocation allowed)
// ---------------------------------------------------------------------------
__device__ int   d_flag;
__device__ float d_deg[NN];
__device__ int   d_rows[EP1];
__device__ int   d_cols[EP1];
__device__ int   d_rowptr[NN + 1];
__device__ int   d_cursor[NN];
__device__ int   d_csr_col[EP1];
__device__ float d_csr_w[EP1];
__device__ int   d_bsum[256];
__device__ int   d_boff[256];
__device__ int   d_rowtmp[NN];

// BN statistics slots: [slot][0..255]=sum, [slot][256..511]=sumsq
// slots: 0-2 conv BN, 3-5 bng, 6-8 bnl
__device__ float d_statsAll[10 * 512];

// fp32 pre-BN tensors
__device__ float bufA[(size_t)NN * HID];   // GEMM out (pre-spmm) / scratch
__device__ float bufB[(size_t)NN * HID];   // spmm out S1/S2, local-head src
__device__ float bufSH[(size_t)NN * HID];  // final GCN h (pre-BN)
__device__ float bufG0[(size_t)NN * HID];
__device__ float bufG1[(size_t)NN * HID];
__device__ float bufG2[(size_t)NN * HID];

// transposed bf16 weights, [N=256, K] per segment (hi/lo split)
#define WT_TOTAL 786432
__device__ __nv_bfloat16 d_wth[WT_TOTAL];
__device__ __nv_bfloat16 d_wtl[WT_TOTAL];

// ---------------------------------------------------------------------------
// mma.sync / ldmatrix helpers (base-target legal)
// ---------------------------------------------------------------------------
__device__ __forceinline__ uint32_t smem_u32(const void* p) {
    uint32_t a;
    asm("{ .reg .u64 t; cvta.to.shared.u64 t, %1; cvt.u32.u64 %0, t; }" : "=r"(a) : "l"(p));
    return a;
}
__device__ __forceinline__ void ldsm4(uint32_t* r, uint32_t addr) {
    asm volatile("ldmatrix.sync.aligned.m8n8.x4.shared.b16 {%0,%1,%2,%3}, [%4];"
                 : "=r"(r[0]), "=r"(r[1]), "=r"(r[2]), "=r"(r[3]) : "r"(addr));
}
__device__ __forceinline__ void mma16816(float* d, const uint32_t* a,
                                         uint32_t b0, uint32_t b1) {
    asm volatile(
        "mma.sync.aligned.m16n8k16.row.col.f32.bf16.bf16.f32 "
        "{%0,%1,%2,%3}, {%4,%5,%6,%7}, {%8,%9}, {%0,%1,%2,%3};"
        : "+f"(d[0]), "+f"(d[1]), "+f"(d[2]), "+f"(d[3])
        : "r"(a[0]), "r"(a[1]), "r"(a[2]), "r"(a[3]), "r"(b0), "r"(b1));
}

// ---------------------------------------------------------------------------
// Preprocessing
// ---------------------------------------------------------------------------
__global__ void zero_pre_kernel() {
    int i = blockIdx.x * blockDim.x + threadIdx.x;
    if (i < NN) { d_deg[i] = 0.0f; d_cursor[i] = 0; }
    if (i < 10 * 512) d_statsAll[i] = 0.0f;
}
__global__ void detect_kernel(const unsigned int* __restrict__ ei) {
    if (threadIdx.x == 0 && blockIdx.x == 0) {
        int is64 = 1;
        for (int k = 0; k < 256; k++)
            if (ei[2 * k + 1] != 0u) { is64 = 0; break; }
        d_flag = is64;
    }
}
__global__ void build_edges_kernel(const void* __restrict__ ei) {
    int e = blockIdx.x * blockDim.x + threadIdx.x;
    if (e >= EP1) return;
    int r, c;
    if (e < EE) {
        if (d_flag) {
            const long long* p = (const long long*)ei;
            r = (int)p[e]; c = (int)p[EE + e];
        } else {
            const int* p = (const int*)ei;
            r = p[e]; c = p[EE + e];
        }
    } else {
        r = c = e - EE;
    }
    d_rows[e] = r;
    d_cols[e] = c;
    atomicAdd(&d_deg[r], 1.0f);
}
__global__ void scan1_kernel() {
    __shared__ int sh[256];
    int b = blockIdx.x, t = threadIdx.x;
    int i = b * 256 + t;
    sh[t] = (i < NN) ? (int)d_deg[i] : 0;
    __syncthreads();
    for (int off = 1; off < 256; off <<= 1) {
        int add = (t >= off) ? sh[t - off] : 0;
        __syncthreads();
        sh[t] += add;
        __syncthreads();
    }
    if (i < NN) d_rowtmp[i] = sh[t];
    if (t == 255) d_bsum[b] = sh[255];
}
__global__ void scan2_kernel() {
    __shared__ int sh[256];
    int t = threadIdx.x;
    sh[t] = (t < 196) ? d_bsum[t] : 0;
    __syncthreads();
    for (int off = 1; off < 256; off <<= 1) {
        int add = (t >= off) ? sh[t - off] : 0;
        __syncthreads();
        sh[t] += add;
        __syncthreads();
    }
    d_boff[t] = (t == 0) ? 0 : sh[t - 1];
}
__global__ void scan3_kernel() {
    int i = blockIdx.x * blockDim.x + threadIdx.x;
    if (i >= NN) return;
    if (i == 0) d_rowptr[0] = 0;
    d_rowptr[i + 1] = d_rowtmp[i] + d_boff[i >> 8];
}
__global__ void csr_build_kernel() {
    int e = blockIdx.x * blockDim.x + threadIdx.x;
    if (e >= EP1) return;
    int r = d_rows[e], c = d_cols[e];
    float w = rsqrtf(d_deg[r]) * rsqrtf(d_deg[c]);
    int pos = d_rowptr[r] + atomicAdd(&d_cursor[r], 1);
    d_csr_col[pos] = c;
    d_csr_w[pos]   = w;
}

// ---------------------------------------------------------------------------
// Weight transpose + bf16 split: Wt[n,k] = W[k,n], hi/lo
// ---------------------------------------------------------------------------
__global__ void wt_kernel(const float* __restrict__ w0, const float* __restrict__ cws,
                          const float* __restrict__ g0, const float* __restrict__ gws,
                          const float* __restrict__ fl)
{
    int i = blockIdx.x * blockDim.x + threadIdx.x;
    if (i >= WT_TOTAL) return;
    const float* src; int K, base;
    if      (i < 131072) { base = 0;      src = w0;            K = 512; }
    else if (i < 196608) { base = 131072; src = cws;           K = 256; }
    else if (i < 262144) { base = 196608; src = cws + 65536;   K = 256; }
    else if (i < 327680) { base = 262144; src = g0;            K = 256; }
    else if (i < 458752) { base = 327680; src = gws;           K = 512; }
    else if (i < 589824) { base = 458752; src = gws + 131072;  K = 512; }
    else if (i < 655360) { base = 589824; src = fl;            K = 256; }
    else if (i < 720896) { base = 655360; src = fl + 65536;    K = 256; }
    else                 { base = 720896; src = fl + 131072;   K = 256; }
    int idx = i - base;
    int n = idx / K, k = idx - n * K;
    float v = src[k * 256 + n];
    __nv_bfloat16 h = __float2bfloat16(v);
    d_wth[i] = h;
    d_wtl[i] = __float2bfloat16(v - __bfloat162float(h));
}

// ---------------------------------------------------------------------------
// Fused GEMM:  C[M,256] = BNrelu(A1|A2)[M,K1+K2] @ Wt^T (+bias) (+stats out)
// A sources are fp32 pre-BN tensors; BN(scale/shift from stats slot)+ReLU+
// bf16 hi/lo split happen inline in the A staging path. 3 precision terms
// (Ah*Wh + Ah*Wl + Al*Wh) accumulate in one fp32 accumulator in a single
// K sweep (Ahi/Alo/Wh/Wl tiles staged together).
// CTA 128x128, 8 warps (4 M x 2 N), BK=32, double-buffered.
// ---------------------------------------------------------------------------
#define GBM 128
#define ASTRIDE 40                         // 32 + 8 pad (bf16 elems)
#define TILE_B  (128 * ASTRIDE * 2)        // 10240 bytes per tile
#define STAGE_B (4 * TILE_B)               // Ahi, Alo, Wh, Wl
#define SMEM_G  (2 * STAGE_B + 4096)       // + sc/sh tables (512 fl each)

__global__ __launch_bounds__(256)
void mma_gemm_kernel(const float* __restrict__ A1, const float* __restrict__ stA1,
                     const float* __restrict__ g1, const float* __restrict__ b1, int K1,
                     const float* __restrict__ A2, const float* __restrict__ stA2,
                     const float* __restrict__ g2, const float* __restrict__ b2, int K2,
                     const __nv_bfloat16* __restrict__ Wh,
                     const __nv_bfloat16* __restrict__ Wl,
                     const float* __restrict__ bias, float* __restrict__ C,
                     float* __restrict__ statsOut, int M)
{
    extern __shared__ char smem[];
    float* sct = (float*)(smem + 2 * STAGE_B);
    float* sht = sct + 512;

    const int tid  = threadIdx.x;
    const int lane = tid & 31;
    const int wid  = tid >> 5;
    const int wm   = wid & 3;
    const int wn   = wid >> 2;
    const int bm   = blockIdx.y * GBM;
    const int bn   = blockIdx.x * 128;
    const int Ktot = K1 + K2;
    const int T    = Ktot >> 5;

    // BN scale/shift tables (identity when stats == null)
    const float invn = 1.0f / (float)NN;
    for (int k = tid; k < Ktot; k += 256) {
        bool s2 = (k >= K1);
        const float* st = s2 ? stA2 : stA1;
        float sc = 1.0f, shv = 0.0f;
        if (st) {
            int kl = s2 ? k - K1 : k;
            const float* gg = s2 ? g2 : g1;
            const float* bb = s2 ? b2 : b1;
            float m = st[kl] * invn;
            float v = st[256 + kl] * invn - m * m;
            sc  = gg[kl] * rsqrtf(v + EPSV);
            shv = bb[kl] - m * sc;
        }
        sct[k] = sc; sht[k] = shv;
    }
    __syncthreads();

    float acc[2][8][4];
#pragma unroll
    for (int i = 0; i < 2; i++)
#pragma unroll
        for (int j = 0; j < 8; j++)
#pragma unroll
            for (int q = 0; q < 4; q++) acc[i][j][q] = 0.0f;

    const int lrow = tid >> 2;            // 0..63
    const int lseg = tid & 3;             // 8 elems each

    float4 fa[2][2];                      // A fp32 staging (2 rows x 8)
    uint4  wv[2][2];                      // W hi/lo staging

    auto g_load = [&](int t) {
        int kk = t << 5;
        const float* Ab; int lda, ko;
        if (kk < K1) { Ab = A1; lda = K1; ko = kk; }
        else         { Ab = A2; lda = K2; ko = kk - K1; }
#pragma unroll
        for (int it = 0; it < 2; it++) {
            int row = lrow + it * 64;
            int gr  = bm + row; if (gr >= M) gr = M - 1;
            const float* p = Ab + (size_t)gr * lda + ko + lseg * 8;
            fa[it][0] = *(const float4*)p;
            fa[it][1] = *(const float4*)(p + 4);
            size_t wo = (size_t)(bn + row) * Ktot + kk + lseg * 8;
            wv[it][0] = *(const uint4*)(Wh + wo);
            wv[it][1] = *(const uint4*)(Wl + wo);
        }
    };
    auto s_store = [&](int t, int buf) {
        int kk = t << 5;
        bool rel = (kk < K1) ? (stA1 != nullptr) : (stA2 != nullptr);
        float scv[8], shv[8];
        *(float4*)&scv[0] = *(const float4*)&sct[kk + lseg * 8];
        *(float4*)&scv[4] = *(const float4*)&sct[kk + lseg * 8 + 4];
        *(float4*)&shv[0] = *(const float4*)&sht[kk + lseg * 8];
        *(float4*)&shv[4] = *(const float4*)&sht[kk + lseg * 8 + 4];
        char* st = smem + buf * STAGE_B;
#pragma unroll
        for (int it = 0; it < 2; it++) {
            int row = lrow + it * 64;
            float v[8];
            *(float4*)&v[0] = fa[it][0];
            *(float4*)&v[4] = fa[it][1];
            uint32_t hp[4], lp[4];
#pragma unroll
            for (int q = 0; q < 4; q++) {
                float y0 = v[2 * q]     * scv[2 * q]     + shv[2 * q];
                float y1 = v[2 * q + 1] * scv[2 * q + 1] + shv[2 * q + 1];
                if (rel) { y0 = fmaxf(y0, 0.0f); y1 = fmaxf(y1, 0.0f); }
                __nv_bfloat162 h2 = __floats2bfloat162_rn(y0, y1);
                hp[q] = *(uint32_t*)&h2;
                float l0 = y0 - __bfloat162float(h2.x);
                float l1 = y1 - __bfloat162float(h2.y);
                __nv_bfloat162 l2 = __floats2bfloat162_rn(l0, l1);
                lp[q] = *(uint32_t*)&l2;
            }
            uint32_t off = (row * ASTRIDE + lseg * 8) * 2;
            *(uint4*)(st + off)              = make_uint4(hp[0], hp[1], hp[2], hp[3]);
            *(uint4*)(st + TILE_B + off)     = make_uint4(lp[0], lp[1], lp[2], lp[3]);
            *(uint4*)(st + 2 * TILE_B + off) = wv[it][0];
            *(uint4*)(st + 3 * TILE_B + off) = wv[it][1];
        }
    };

    const uint32_t smb  = smem_u32(smem);
    const uint32_t aoff = ((wm * 32 + (lane & 15)) * ASTRIDE + (lane >> 4) * 8) * 2;
    const uint32_t boff = ((wn * 64 + (lane & 7) + ((lane >> 4) << 3)) * ASTRIDE
                           + ((lane >> 3) & 1) * 8) * 2;

    g_load(0);
    s_store(0, 0);
    __syncthreads();

    for (int t = 0; t < T; t++) {
        const int buf = t & 1;
        if (t + 1 < T) g_load(t + 1);
        const uint32_t base = smb + buf * STAGE_B;
#pragma unroll
        for (int ks = 0; ks < 2; ks++) {
            uint32_t ahi[2][4], alo[2][4];
#pragma unroll
            for (int i = 0; i < 2; i++) {
                ldsm4(ahi[i], base + aoff + i * (16 * ASTRIDE * 2) + ks * 32);
                ldsm4(alo[i], base + TILE_B + aoff + i * (16 * ASTRIDE * 2) + ks * 32);
            }
            uint32_t bh[4][4], bl[4][4];
#pragma unroll
            for (int j = 0; j < 4; j++) {
                ldsm4(bh[j], base + 2 * TILE_B + boff + j * (16 * ASTRIDE * 2) + ks * 32);
                ldsm4(bl[j], base + 3 * TILE_B + boff + j * (16 * ASTRIDE * 2) + ks * 32);
            }
#pragma unroll
            for (int i = 0; i < 2; i++)
#pragma unroll
                for (int j = 0; j < 4; j++) {
                    mma16816(acc[i][2 * j + 0], ahi[i], bh[j][0], bh[j][1]);
                    mma16816(acc[i][2 * j + 1], ahi[i], bh[j][2], bh[j][3]);
                    mma16816(acc[i][2 * j + 0], ahi[i], bl[j][0], bl[j][1]);
                    mma16816(acc[i][2 * j + 1], ahi[i], bl[j][2], bl[j][3]);
                    mma16816(acc[i][2 * j + 0], alo[i], bh[j][0], bh[j][1]);
                    mma16816(acc[i][2 * j + 1], alo[i], bh[j][2], bh[j][3]);
                }
        }
        if (t + 1 < T) s_store(t + 1, buf ^ 1);
        __syncthreads();
    }

    // ---- epilogue: bias + store + (optional) fused BN stats ----
    float* ss = (float*)smem;             // reuse stage area (synced above)
    if (statsOut) {
        for (int i2 = tid; i2 < 512; i2 += 256) ss[i2] = 0.0f;
    }
    __syncthreads();

#pragma unroll
    for (int i = 0; i < 2; i++) {
        int r0 = bm + wm * 32 + i * 16 + (lane >> 2);
#pragma unroll
        for (int j = 0; j < 8; j++) {
            int col = bn + wn * 64 + j * 8 + (lane & 3) * 2;
            float b0 = bias ? bias[col]     : 0.0f;
            float b1 = bias ? bias[col + 1] : 0.0f;
            bool v0 = (r0 < M), v1 = (r0 + 8 < M);
            float y00 = v0 ? acc[i][j][0] + b0 : 0.0f;
            float y01 = v0 ? acc[i][j][1] + b1 : 0.0f;
            float y10 = v1 ? acc[i][j][2] + b0 : 0.0f;
            float y11 = v1 ? acc[i][j][3] + b1 : 0.0f;
            if (v0) { float2 w = { y00, y01 }; *(float2*)(C + (size_t)r0 * 256 + col) = w; }
            if (v1) { float2 w = { y10, y11 }; *(float2*)(C + (size_t)(r0 + 8) * 256 + col) = w; }
            if (statsOut) {
                float s0 = y00 + y10, s1 = y01 + y11;
                float q0 = y00 * y00 + y10 * y10, q1 = y01 * y01 + y11 * y11;
#pragma unroll
                for (int off = 4; off < 32; off <<= 1) {
                    s0 += __shfl_xor_sync(0xffffffffu, s0, off);
                    s1 += __shfl_xor_sync(0xffffffffu, s1, off);
                    q0 += __shfl_xor_sync(0xffffffffu, q0, off);
                    q1 += __shfl_xor_sync(0xffffffffu, q1, off);
                }
                if ((lane >> 2) == 0) {
                    atomicAdd(&ss[col],           s0);
                    atomicAdd(&ss[col + 1],       s1);
                    atomicAdd(&ss[256 + col],     q0);
                    atomicAdd(&ss[256 + col + 1], q1);
                }
            }
        }
    }
    if (statsOut) {
        __syncthreads();
        for (int c = tid; c < 256; c += 256) {
            atomicAdd(&statsOut[c],       ss[c]);
            atomicAdd(&statsOut[256 + c], ss[256 + c]);
        }
    }
}

// ---------------------------------------------------------------------------
// SpMM (CSR, warp per row): dst[r,:] = sum_e w_e * src[col_e,:] + bias[:]
// ---------------------------------------------------------------------------
__global__ void spmm_kernel(const float* __restrict__ src,
                            const float* __restrict__ bias,
                            float* __restrict__ dst)
{
    int gw   = (blockIdx.x * blockDim.x + threadIdx.x) >> 5;
    int lane = threadIdx.x & 31;
    if (gw >= NN) return;
    int beg = d_rowptr[gw], end = d_rowptr[gw + 1];
    float acc[8] = {0, 0, 0, 0, 0, 0, 0, 0};
    for (int e = beg; e < end; e++) {
        int   cidx = d_csr_col[e];
        float w    = d_csr_w[e];
        const float* p = src + (size_t)cidx * HID;
#pragma unroll
        for (int k = 0; k < 8; k++) acc[k] += w * p[lane + 32 * k];
    }
    float* o = dst + (size_t)gw * HID;
#pragma unroll
    for (int k = 0; k < 8; k++) o[lane + 32 * k] = acc[k] + bias[lane + 32 * k];
}

// stats for SpMM outputs
__global__ void stats_kernel(const float* __restrict__ src, float* __restrict__ statsOut) {
    int c  = threadIdx.x;
    int r0 = blockIdx.x * 64;
    int r1 = r0 + 64; if (r1 > NN) r1 = NN;
    float s = 0.0f, s2 = 0.0f;
    for (int r = r0; r < r1; r++) {
        float v = src[(size_t)r * HID + c];
        s += v; s2 += v * v;
    }
    atomicAdd(&statsOut[c], s);
    atomicAdd(&statsOut[256 + c], s2);
}

// ---------------------------------------------------------------------------
// Head: out[hidx, r, :] = log_softmax(relu(bn(src))[r,:] @ W[256,2] + b)
// ---------------------------------------------------------------------------
__global__ void head_kernel(const float* __restrict__ src,
                            const float* __restrict__ stats,
                            const float* __restrict__ g, const float* __restrict__ bb,
                            const float* __restrict__ W,
                            const float* __restrict__ bh,
                            float* __restrict__ out, int hidx)
{
    int gw   = (blockIdx.x * blockDim.x + threadIdx.x) >> 5;
    int lane = threadIdx.x & 31;
    if (gw >= NN) return;
    const float* sp = src + (size_t)gw * HID;
    const float invn = 1.0f / (float)NN;
    float a0 = 0.0f, a1 = 0.0f;
#pragma unroll
    for (int k = lane; k < HID; k += 32) {
        float m  = stats[k] * invn;
        float vv = stats[256 + k] * invn - m * m;
        float sc = g[k] * rsqrtf(vv + EPSV);
        float v  = fmaxf((sp[k] - m) * sc + bb[k], 0.0f);
        a0 += v * W[2 * k];
        a1 += v * W[2 * k + 1];
    }
#pragma unroll
    for (int off = 16; off; off >>= 1) {
        a0 += __shfl_down_sync(0xffffffffu, a0, off);
        a1 += __shfl_down_sync(0xffffffffu, a1, off);
    }
    if (lane == 0) {
        float z0 = a0 + bh[0], z1 = a1 + bh[1];
        float m  = fmaxf(z0, z1);
        float l  = m + logf(expf(z0 - m) + expf(z1 - m));
        float* o = out + ((size_t)hidx * NN + gw) * 2;
        o[0] = z0 - l;
        o[1] = z1 - l;
    }
}

// ---------------------------------------------------------------------------
// Host launcher
// ---------------------------------------------------------------------------
extern "C" void kernel_launch(void* const* d_in, const int* in_sizes, int n_in,
                              void* d_out, int out_size)
{
    const float* x       = (const float*)d_in[0];
    const void*  ei      = d_in[1];
    const float* conv_w0 = (const float*)d_in[2];
    const float* conv_ws = (const float*)d_in[3];
    const float* conv_b  = (const float*)d_in[4];
    const float* bn_g    = (const float*)d_in[5];
    const float* bn_b    = (const float*)d_in[6];
    const float* fcg_w0  = (const float*)d_in[7];
    const float* fcg_ws  = (const float*)d_in[8];
    const float* fcg_b   = (const float*)d_in[9];
    const float* bng_g   = (const float*)d_in[10];
    const float* bng_b   = (const float*)d_in[11];
    const float* fcl_w   = (const float*)d_in[12];
    const float* fcl_b   = (const float*)d_in[13];
    const float* bnl_g   = (const float*)d_in[14];
    const float* bnl_b   = (const float*)d_in[15];
    const float* outg_w  = (const float*)d_in[16];
    const float* outg_b  = (const float*)d_in[17];
    const float* outl_w  = (const float*)d_in[18];
    const float* outl_b  = (const float*)d_in[19];
    float* out = (float*)d_out;

    float *pA, *pB, *pSH, *pG0, *pG1, *pG2, *pST;
    __nv_bfloat16 *pWh, *pWl;
    cudaGetSymbolAddress((void**)&pA,  bufA);
    cudaGetSymbolAddress((void**)&pB,  bufB);
    cudaGetSymbolAddress((void**)&pSH, bufSH);
    cudaGetSymbolAddress((void**)&pG0, bufG0);
    cudaGetSymbolAddress((void**)&pG1, bufG1);
    cudaGetSymbolAddress((void**)&pG2, bufG2);
    cudaGetSymbolAddress((void**)&pST, d_statsAll);
    cudaGetSymbolAddress((void**)&pWh, d_wth);
    cudaGetSymbolAddress((void**)&pWl, d_wtl);

    cudaFuncSetAttribute(mma_gemm_kernel,
                         cudaFuncAttributeMaxDynamicSharedMemorySize, SMEM_G);

    // ---- preprocessing (also zeroes all stats slots) ----
    zero_pre_kernel<<<(NN + 255) / 256, 256>>>();
    detect_kernel<<<1, 32>>>((const unsigned int*)ei);
    build_edges_kernel<<<(EP1 + 255) / 256, 256>>>(ei);
    scan1_kernel<<<196, 256>>>();
    scan2_kernel<<<1, 256>>>();
    scan3_kernel<<<(NN + 255) / 256, 256>>>();
    csr_build_kernel<<<(EP1 + 255) / 256, 256>>>();
    wt_kernel<<<(WT_TOTAL + 255) / 256, 256>>>(conv_w0, conv_ws, fcg_w0, fcg_ws, fcl_w);

    dim3 gg(2, (NN + GBM - 1) / GBM);
    const int spmm_grid = (NN + 7) / 8;
    const int head_grid = (NN + 7) / 8;

    // weight-table offsets
    const int W0 = 0, C1 = 131072, C2 = 196608, G0 = 262144,
              GW0 = 327680, GW1 = 458752, L0 = 589824;

    // stats slots
    float* st0 = pST;              // conv BN 0
    float* st1 = pST + 512;        // conv BN 1
    float* st2 = pST + 1024;       // conv BN 2 (final h)
    float* sg0 = pST + 1536;       // bng 0
    float* sg1 = pST + 2048;       // bng 1
    float* sg2 = pST + 2560;       // bng 2
    float* sl0 = pST + 3072;       // bnl 0..2
    float* sl1 = pST + 3584;
    float* sl2 = pST + 4096;

    // ---- GCN layer 0 (A = x, identity) ----
    mma_gemm_kernel<<<gg, 256, SMEM_G>>>(x, nullptr, nullptr, nullptr, INC,
                                         nullptr, nullptr, nullptr, nullptr, 0,
                                         pWh + W0, pWl + W0, nullptr, pA, nullptr, NN);
    spmm_kernel<<<spmm_grid, 256>>>(pA, conv_b, pB);
    stats_kernel<<<(NN + 63) / 64, 256>>>(pB, st0);

    // ---- GCN layer 1 ----
    mma_gemm_kernel<<<gg, 256, SMEM_G>>>(pB, st0, bn_g, bn_b, HID,
                                         nullptr, nullptr, nullptr, nullptr, 0,
                                         pWh + C1, pWl + C1, nullptr, pA, nullptr, NN);
    spmm_kernel<<<spmm_grid, 256>>>(pA, conv_b + HID, pB);
    stats_kernel<<<(NN + 63) / 64, 256>>>(pB, st1);

    // ---- GCN layer 2 ----
    mma_gemm_kernel<<<gg, 256, SMEM_G>>>(pB, st1, bn_g + HID, bn_b + HID, HID,
                                         nullptr, nullptr, nullptr, nullptr, 0,
                                         pWh + C2, pWl + C2, nullptr, pA, nullptr, NN);
    spmm_kernel<<<spmm_grid, 256>>>(pA, conv_b + 2 * HID, pSH);
    stats_kernel<<<(NN + 63) / 64, 256>>>(pSH, st2);

    // ---- global path ----
    mma_gemm_kernel<<<gg, 256, SMEM_G>>>(pSH, st2, bn_g + 2 * HID, bn_b + 2 * HID, HID,
                                         nullptr, nullptr, nullptr, nullptr, 0,
                                         pWh + G0, pWl + G0, fcg_b, pG0, sg0, NN);
    // xg1 = [hg0, h] @ gw0
    mma_gemm_kernel<<<gg, 256, SMEM_G>>>(pG0, sg0, bng_g, bng_b, HID,
                                         pSH, st2, bn_g + 2 * HID, bn_b + 2 * HID, HID,
                                         pWh + GW0, pWl + GW0, fcg_b + HID, pG1, sg1, NN);
    // xg2 = [hg1, h] @ gw1
    mma_gemm_kernel<<<gg, 256, SMEM_G>>>(pG1, sg1, bng_g + HID, bng_b + HID, HID,
                                         pSH, st2, bn_g + 2 * HID, bn_b + 2 * HID, HID,
                                         pWh + GW1, pWl + GW1, fcg_b + 2 * HID, pG2, sg2, NN);

    // ---- global head ----
    head_kernel<<<head_grid, 256>>>(pG2, sg2, bng_g + 2 * HID, bng_b + 2 * HID,
                                    outg_w, outg_b, out, 0);

    // ---- local heads ----
    float* gsrc[3]  = { pG0, pG1, pG2 };
    float* gstat[3] = { sg0, sg1, sg2 };
    float* lstat[3] = { sl0, sl1, sl2 };
    for (int i = 0; i < 3; i++) {
        mma_gemm_kernel<<<gg, 256, SMEM_G>>>(gsrc[i], gstat[i],
                                             bng_g + (size_t)i * HID, bng_b + (size_t)i * HID, HID,
                                             nullptr, nullptr, nullptr, nullptr, 0,
                                             pWh + L0 + i * 65536, pWl + L0 + i * 65536,
                                             fcl_b + (size_t)i * HID, pB, lstat[i], NN);
        head_kernel<<<head_grid, 256>>>(pB, lstat[i],
                                        bnl_g + (size_t)i * HID, bnl_b + (size_t)i * HID,
                                        outl_w + (size_t)i * HID * OUTC,
                                        outl_b + (size_t)i * OUTC, out, 1 + i);
    }
}